// round 16
// baseline (speedup 1.0000x reference)
#include <cuda_runtime.h>
#include <cuda_bf16.h>
#include <cstdint>

// Problem constants
#define NBATCH   16384
#define NAG      32
#define NOBS     64
#define NH       64
#define NACT     16
#define NROUNDS  2

#define NUNITS   NBATCH        // work unit = one batch (32 rows) per warp
#define NTHREADS 512           // 16 warps -> 4/SMSP (reg cap 128)
#define NCTAS    152           // persistent: 1 CTA per SM

// SMEM weight strides (bf16 elements); conflict-free LDSM
#define W_STRIDE  72
#define W2_STRIDE 24

// Persistent work counter. Static-init 0; every launch leaves it at 0 again
// (each warp atomicSubs exactly the number of atomicAdd fetches it made, so
// sum(adds) == sum(subs) for any interleaving). Transient duplicate unit ids
// after some warp exits recompute byte-identical output -> harmless.
__device__ unsigned g_tile_ctr = 0;

// ---------------------------------------------------------------------------
// PTX helpers
// ---------------------------------------------------------------------------
__device__ __forceinline__ uint32_t smem_u32(const void* p) {
    return (uint32_t)__cvta_generic_to_shared(p);
}
__device__ __forceinline__ void l2pf(const void* p) {
    asm volatile("prefetch.global.L2 [%0];" :: "l"(p));
}

__device__ __forceinline__ void ldsm_x4_t(uint32_t& r0, uint32_t& r1, uint32_t& r2, uint32_t& r3, uint32_t a) {
    asm volatile("ldmatrix.sync.aligned.m8n8.x4.trans.shared.b16 {%0,%1,%2,%3}, [%4];"
                 : "=r"(r0), "=r"(r1), "=r"(r2), "=r"(r3) : "r"(a));
}
__device__ __forceinline__ void mma16816(float* c,
                                         uint32_t a0, uint32_t a1, uint32_t a2, uint32_t a3,
                                         uint32_t b0, uint32_t b1) {
    asm volatile("mma.sync.aligned.m16n8k16.row.col.f32.bf16.bf16.f32 "
                 "{%0,%1,%2,%3}, {%4,%5,%6,%7}, {%8,%9}, {%0,%1,%2,%3};"
                 : "+f"(c[0]), "+f"(c[1]), "+f"(c[2]), "+f"(c[3])
                 : "r"(a0), "r"(a1), "r"(a2), "r"(a3), "r"(b0), "r"(b1));
}

__device__ __forceinline__ uint32_t packbf(float x, float y) {
    __nv_bfloat162 p = __floats2bfloat162_rn(x, y);
    return *(uint32_t*)&p;
}
__device__ __forceinline__ uint32_t bf2add(uint32_t a, uint32_t b) {
    __nv_bfloat162 r = __hadd2(*(__nv_bfloat162*)&a, *(__nv_bfloat162*)&b);
    return *(uint32_t*)&r;
}

// One K=16 step, single A fragment, NT n-tiles (8 cols each)
template <int NT>
__device__ __forceinline__ void gemm_ktile(const uint32_t a[4],
                                           const __nv_bfloat16* sWk, int wstride,
                                           float acc[][4], int lane) {
#pragma unroll
    for (int nt = 0; nt < NT; nt += 2) {
        uint32_t b0, b1, b2, b3;
        ldsm_x4_t(b0, b1, b2, b3,
                  smem_u32(sWk + (lane & 15) * wstride + nt * 8 + ((lane >> 4) << 3)));
        mma16816(acc[nt], a[0], a[1], a[2], a[3], b0, b1);
        if (nt + 1 < NT) mma16816(acc[nt + 1], a[0], a[1], a[2], a[3], b2, b3);
    }
}

// One K=16 step for two stripes: B loaded once, used by 2 A fragments.
template <int NT>
__device__ __forceinline__ void gemm2_ktile(const uint32_t a0[4], const uint32_t a1[4],
                                            const __nv_bfloat16* sWk, int wstride,
                                            float acc0[][4], float acc1[][4], int lane) {
#pragma unroll
    for (int nt = 0; nt < NT; nt += 2) {
        uint32_t b0, b1, b2, b3;
        ldsm_x4_t(b0, b1, b2, b3,
                  smem_u32(sWk + (lane & 15) * wstride + nt * 8 + ((lane >> 4) << 3)));
        mma16816(acc0[nt], a0[0], a0[1], a0[2], a0[3], b0, b1);
        mma16816(acc1[nt], a1[0], a1[1], a1[2], a1[3], b0, b1);
        if (nt + 1 < NT) {
            mma16816(acc0[nt + 1], a0[0], a0[1], a0[2], a0[3], b2, b3);
            mma16816(acc1[nt + 1], a1[0], a1[1], a1[2], a1[3], b2, b3);
        }
    }
}

// bias + relu + pack a 32-col half (acc[4][4]) into 2 A-frag k-tiles (bf16x2 ops).
__device__ __forceinline__ void pack_h4(const float acc[][4], uint32_t hf[][4],
                                        const uint32_t* sBH, int c) {
    const __nv_bfloat162 z = __float2bfloat162_rn(0.0f);
#pragma unroll
    for (int tt = 0; tt < 2; ++tt) {
        uint32_t bA = sBH[8 * tt + c];
        uint32_t bB = sBH[8 * tt + 4 + c];
#pragma unroll
        for (int j = 0; j < 2; ++j) {
            uint32_t pa = packbf(acc[2*tt][2*j],   acc[2*tt][2*j + 1]);
            uint32_t pb = packbf(acc[2*tt+1][2*j], acc[2*tt+1][2*j + 1]);
            __nv_bfloat162 ra = __hmax2(__hadd2(*(__nv_bfloat162*)&pa, *(__nv_bfloat162*)&bA), z);
            __nv_bfloat162 rb = __hmax2(__hadd2(*(__nv_bfloat162*)&pb, *(__nv_bfloat162*)&bB), z);
            hf[tt][j]     = *(uint32_t*)&ra;
            hf[tt][2 + j] = *(uint32_t*)&rb;
        }
    }
}

// Direct obs A-fragment gather (LDG.64 per fragment pair; L2-prefetched, no shfl)
__device__ __forceinline__ void enc_frags(const float* __restrict__ obs,
                                          size_t rbase_row, int t,
                                          int gr, int c, uint32_t a[4]) {
    const float* p = obs + (rbase_row + gr) * NOBS + 16 * t + 2 * c;
    float2 v0 = __ldg((const float2*)(p));
    float2 v1 = __ldg((const float2*)(p + 8 * NOBS));
    float2 v2 = __ldg((const float2*)(p + 8));
    float2 v3 = __ldg((const float2*)(p + 8 * NOBS + 8));
    a[0] = packbf(v0.x, v0.y);
    a[1] = packbf(v1.x, v1.y);
    a[2] = packbf(v2.x, v2.y);
    a[3] = packbf(v3.x, v3.y);
}

// Dense relu layer, N split into two 32-col halves (acc stays 32 regs)
__device__ __forceinline__ void dense64(const uint32_t (&ain)[2][4][4],
                                        uint32_t (&hout)[2][4][4],
                                        const __nv_bfloat16* W, const uint32_t* sBH,
                                        int lane, int c) {
#pragma unroll
    for (int nh = 0; nh < 2; ++nh) {
        float acc[2][4][4];
#pragma unroll
        for (int st = 0; st < 2; ++st)
#pragma unroll
            for (int nt = 0; nt < 4; ++nt) {
                acc[st][nt][0]=0.f; acc[st][nt][1]=0.f; acc[st][nt][2]=0.f; acc[st][nt][3]=0.f;
            }
#pragma unroll
        for (int t = 0; t < 4; ++t)
            gemm2_ktile<4>(ain[0][t], ain[1][t], W + 16 * t * W_STRIDE + 32 * nh, W_STRIDE,
                           acc[0], acc[1], lane);
        pack_h4(acc[0], &hout[0][2 * nh], sBH + 16 * nh, c);
        pack_h4(acc[1], &hout[1][2 * nh], sBH + 16 * nh, c);
    }
}

// Comm round (rank-1 decomposed). Column sums entirely in packed bf16 (HADD2).
__device__ __forceinline__ void comm_round(const uint32_t (&hin)[2][4][4],
                                           uint32_t (&hout)[2][4][4],
                                           const __nv_bfloat16* Wc1, const __nv_bfloat16* Wc2,
                                           const uint32_t* sBH, int lane, int c) {
    uint32_t csPA[4], csPB[4];
#pragma unroll
    for (int t = 0; t < 4; ++t) {
        uint32_t pA = bf2add(bf2add(hin[0][t][0], hin[0][t][1]),
                             bf2add(hin[1][t][0], hin[1][t][1]));
        uint32_t pB = bf2add(bf2add(hin[0][t][2], hin[0][t][3]),
                             bf2add(hin[1][t][2], hin[1][t][3]));
#pragma unroll
        for (int m = 4; m < 32; m <<= 1) {
            pA = bf2add(pA, __shfl_xor_sync(0xffffffffu, pA, m));
            pB = bf2add(pB, __shfl_xor_sync(0xffffffffu, pB, m));
        }
        csPA[t] = pA;
        csPB[t] = pB;
    }

#pragma unroll
    for (int nh = 0; nh < 2; ++nh) {
        // R = cs @ W2' (replicated-A, row-invariant) for this half
        float racc[4][4];
#pragma unroll
        for (int nt = 0; nt < 4; ++nt) {
            racc[nt][0]=0.f; racc[nt][1]=0.f; racc[nt][2]=0.f; racc[nt][3]=0.f;
        }
#pragma unroll
        for (int t = 0; t < 4; ++t) {
            uint32_t a[4];
            a[0] = csPA[t]; a[1] = csPA[t];
            a[2] = csPB[t]; a[3] = csPB[t];
            gemm_ktile<4>(a, Wc2 + 16 * t * W_STRIDE + 32 * nh, W_STRIDE, racc, lane);
        }
        // acc = R (all rows equal) + h @ W1'
        float acc[2][4][4];
#pragma unroll
        for (int st = 0; st < 2; ++st)
#pragma unroll
            for (int nt = 0; nt < 4; ++nt) {
                acc[st][nt][0]=racc[nt][0]; acc[st][nt][1]=racc[nt][1];
                acc[st][nt][2]=racc[nt][2]; acc[st][nt][3]=racc[nt][3];
            }
#pragma unroll
        for (int t = 0; t < 4; ++t)
            gemm2_ktile<4>(hin[0][t], hin[1][t], Wc1 + 16 * t * W_STRIDE + 32 * nh, W_STRIDE,
                           acc[0], acc[1], lane);
        pack_h4(acc[0], &hout[0][2 * nh], sBH + 16 * nh, c);
        pack_h4(acc[1], &hout[1][2 * nh], sBH + 16 * nh, c);
    }
}

// ---------------------------------------------------------------------------
// Persistent warp-autonomous CommNet kernel: 16 warps, 1 batch/warp, N-split.
// Single launch: weights are converted fp32->bf16 (incl. rank-1 decomposition)
// directly into SMEM in the prologue; self-cleaning work counter.
// ---------------------------------------------------------------------------
__global__ void __launch_bounds__(NTHREADS, 1)
commnet_kernel(const float* __restrict__ obs,
               const float* __restrict__ enc_w,
               const float* __restrict__ enc_b,
               const float* __restrict__ comm_w,
               const float* __restrict__ comm_b,
               const float* __restrict__ out_w1,
               const float* __restrict__ out_b1,
               const float* __restrict__ out_w2,
               const float* __restrict__ out_b2,
               const int*   __restrict__ avail,
               float*       __restrict__ out) {
    extern __shared__ __align__(16) char smem_raw[];
    __nv_bfloat16* sWe  = (__nv_bfloat16*)smem_raw;                  // 64  x 72
    __nv_bfloat16* sWc1 = sWe  + NH * W_STRIDE;                      // 128 x 72 (2 rounds)
    __nv_bfloat16* sWc2 = sWc1 + NROUNDS * NH * W_STRIDE;            // 128 x 72 (2 rounds)
    __nv_bfloat16* sWo1 = sWc2 + NROUNDS * NH * W_STRIDE;            // 64  x 72
    __nv_bfloat16* sWo2 = sWo1 + NH * W_STRIDE;                      // 64  x 24
    uint32_t*      sBH  = (uint32_t*)(sWo2 + NH * W2_STRIDE);        // 128 bf16x2 pairs
    float*         sB2  = (float*)(sBH + 128);                       // 16 fp32 (out_b2)

    const int tid  = threadIdx.x;
    const int lane = tid & 31;
    const int c    = lane & 3;
    const int gr   = lane >> 2;

    // ---- prologue: convert fp32 weights directly into SMEM ----
    for (int i = tid; i < NOBS * NH; i += NTHREADS) {
        int r = i >> 6, j = i & 63;
        sWe[r * W_STRIDE + j] = __float2bfloat16(enc_w[i]);
    }
    for (int i = tid; i < NROUNDS * NH * NH; i += NTHREADS) {
        int rd = i >> 12, k = (i >> 6) & 63, j = i & 63;
        float top = comm_w[rd * 2 * NH * NH + k * NH + j];
        float bot = comm_w[rd * 2 * NH * NH + (NH + k) * NH + j];
        sWc1[(rd * NH + k) * W_STRIDE + j] = __float2bfloat16(top - bot * (1.0f / 31.0f));
        sWc2[(rd * NH + k) * W_STRIDE + j] = __float2bfloat16(bot * (1.0f / 31.0f));
    }
    for (int i = tid; i < NH * NH; i += NTHREADS) {
        int r = i >> 6, j = i & 63;
        sWo1[r * W_STRIDE + j] = __float2bfloat16(out_w1[i]);
    }
    for (int i = tid; i < NH * NACT; i += NTHREADS) {
        int r = i >> 4, j = i & 15;
        sWo2[r * W2_STRIDE + j] = __float2bfloat16(out_w2[i]);
    }
    // bias pairs: enc [0..32), comm rd0 [32..64), comm rd1 [64..96), out1 [96..128)
    if (tid < 32) sBH[tid]      = packbf(enc_b[2*tid],  enc_b[2*tid+1]);
    if (tid < 64) sBH[32 + tid] = packbf(comm_b[2*tid], comm_b[2*tid+1]);
    if (tid < 32) sBH[96 + tid] = packbf(out_b1[2*tid], out_b1[2*tid+1]);
    if (tid < 16) sB2[tid]      = out_b2[tid];
    __syncthreads();

    // ---- per-warp batch loop (self-cleaning counter) ----
    unsigned b, fetches = 1;
    if (lane == 0) b = atomicAdd(&g_tile_ctr, 1u);
    b = __shfl_sync(0xffffffffu, b, 0);

    uint32_t hA[2][4][4], hB[2][4][4];   // ping-pong activation fragments

    while (b < NUNITS) {
        const size_t row0 = (size_t)b * NAG;

        // ---- encoder: hA = relu(obs @ enc_w + enc_b) ----
        {
            uint32_t ofrag[2][4][4];
#pragma unroll
            for (int t = 0; t < 4; ++t) {
                enc_frags(obs, row0,      t, gr, c, ofrag[0][t]);
                enc_frags(obs, row0 + 16, t, gr, c, ofrag[1][t]);
            }
            dense64(ofrag, hA, sWe, sBH, lane, c);
        }

        // ---- grab next batch, prefetch its obs+avail to L2 ----
        unsigned bn;
        if (lane == 0) bn = atomicAdd(&g_tile_ctr, 1u);
        bn = __shfl_sync(0xffffffffu, bn, 0);
        fetches++;
        if (bn < NUNITS) {
            const char* ob = (const char*)(obs + (size_t)bn * NAG * NOBS);
#pragma unroll
            for (int i = 0; i < 2; ++i) l2pf(ob + lane * 128 + i * 4096);
            if (lane < 16) l2pf((const char*)(avail + (size_t)bn * NAG * NACT) + lane * 128);
        }

        // ---- comm rounds: hA -> hB -> hA ----
        comm_round(hA, hB, sWc1,                 sWc2,                 sBH + 32, lane, c);
        comm_round(hB, hA, sWc1 + NH * W_STRIDE, sWc2 + NH * W_STRIDE, sBH + 64, lane, c);

        // ---- out1: hB = relu(hA @ out_w1 + out_b1) ----
        dense64(hA, hB, sWo1, sBH + 96, lane, c);

        // ---- hoist avail loads (overlap L2 latency with out2 MMAs) ----
        int2 av[2][2][2];
        {
            int colb = 2 * c;
#pragma unroll
            for (int st = 0; st < 2; ++st)
#pragma unroll
                for (int nt = 0; nt < 2; ++nt)
#pragma unroll
                    for (int half = 0; half < 2; ++half) {
                        size_t grow = row0 + st * 16 + gr + 8 * half;
                        av[st][nt][half] = __ldg((const int2*)(avail + grow * NACT + nt * 8 + colb));
                    }
        }

        // ---- out2 from hB: q = hid @ out_w2 + out_b2, mask, store ----
        float acc2[2][2][4];
#pragma unroll
        for (int st = 0; st < 2; ++st)
#pragma unroll
            for (int nt = 0; nt < 2; ++nt) {
                acc2[st][nt][0]=0.f; acc2[st][nt][1]=0.f; acc2[st][nt][2]=0.f; acc2[st][nt][3]=0.f;
            }
#pragma unroll
        for (int t = 0; t < 4; ++t) {
            uint32_t b0, b1, b2, b3;
            ldsm_x4_t(b0, b1, b2, b3,
                      smem_u32(sWo2 + (16 * t + (lane & 15)) * W2_STRIDE + ((lane >> 4) << 3)));
#pragma unroll
            for (int st = 0; st < 2; ++st) {
                const uint32_t* A = hB[st][t];
                mma16816(acc2[st][0], A[0], A[1], A[2], A[3], b0, b1);
                mma16816(acc2[st][1], A[0], A[1], A[2], A[3], b2, b3);
            }
        }

        // ---- epilogue: bias + mask + store ----
        {
            int colb = 2 * c;
#pragma unroll
            for (int st = 0; st < 2; ++st) {
                size_t rowb = row0 + st * 16;
#pragma unroll
                for (int nt = 0; nt < 2; ++nt) {
                    int col  = nt * 8 + colb;
                    float b0 = sB2[col], b1 = sB2[col + 1];
#pragma unroll
                    for (int half = 0; half < 2; ++half) {
                        size_t grow = rowb + gr + 8 * half;
                        int2 a = av[st][nt][half];
                        float q0 = acc2[st][nt][half * 2 + 0] + b0;
                        float q1 = acc2[st][nt][half * 2 + 1] + b1;
                        if (a.x == 0) q0 = -1e10f;
                        if (a.y == 0) q1 = -1e10f;
                        *(float2*)(out + grow * NACT + col) = make_float2(q0, q1);
                    }
                }
            }
        }

        b = bn;
    }

    // restore counter: subtract exactly what this warp added (any interleaving
    // sums to zero across all warps; duplicates recompute identical output)
    if (lane == 0) atomicSub(&g_tile_ctr, fetches);
}

#define SMEM_BYTES ((64*72 + 2*64*72 + 2*64*72 + 64*72 + 64*24) * 2 + 128 * 4 + 16 * 4 + 64)

// ---------------------------------------------------------------------------
extern "C" void kernel_launch(void* const* d_in, const int* in_sizes, int n_in,
                              void* d_out, int out_size) {
    const float* obs    = (const float*)d_in[0];
    const float* enc_w  = (const float*)d_in[1];
    const float* enc_b  = (const float*)d_in[2];
    const float* comm_w = (const float*)d_in[3];
    const float* comm_b = (const float*)d_in[4];
    const float* out_w1 = (const float*)d_in[5];
    const float* out_b1 = (const float*)d_in[6];
    const float* out_w2 = (const float*)d_in[7];
    const float* out_b2 = (const float*)d_in[8];
    const int*   avail  = (const int*)d_in[9];
    float* out = (float*)d_out;

    cudaFuncSetAttribute(commnet_kernel, cudaFuncAttributeMaxDynamicSharedMemorySize, SMEM_BYTES);

    commnet_kernel<<<NCTAS, NTHREADS, SMEM_BYTES>>>(
        obs, enc_w, enc_b, comm_w, comm_b, out_w1, out_b1, out_w2, out_b2, avail, out);
}

// round 17
// speedup vs baseline: 341.2019x; 341.2019x over previous
#include <cuda_runtime.h>
#include <cuda_bf16.h>
#include <cstdint>

// Problem constants
#define NBATCH   16384
#define NAG      32
#define NOBS     64
#define NH       64
#define NACT     16
#define NROUNDS  2

#define NUNITS   NBATCH        // work unit = one batch (32 rows) per warp
#define NTHREADS 512           // 16 warps -> 4/SMSP (reg cap 128)
#define NCTAS    152           // persistent: 1 CTA per SM

// SMEM weight strides (bf16 elements); conflict-free LDSM
#define W_STRIDE  72
#define W2_STRIDE 24

// ---------------------------------------------------------------------------
// Globals: bf16 weights (prologue-converted/decomposed) + persistent work counter
//   comm decomposition: [h|msg] @ Wc == h @ W1' + cs @ W2'
//   W1' = Wc_top - Wc_bot/31,  W2' = Wc_bot/31,  cs = per-batch column sum of h
// Counter is reset by the convert kernel BEFORE the main kernel runs (safe).
// ---------------------------------------------------------------------------
__device__ __nv_bfloat16 g_enc_w  [NOBS * NH];
__device__ __nv_bfloat16 g_comm_w1[NROUNDS * NH * NH];
__device__ __nv_bfloat16 g_comm_w2[NROUNDS * NH * NH];
__device__ __nv_bfloat16 g_out_w1 [NH * NH];
__device__ __nv_bfloat16 g_out_w2 [NH * NACT];
__device__ unsigned      g_tile_ctr;

__global__ void convert_weights_kernel(const float* __restrict__ enc_w,
                                       const float* __restrict__ comm_w,
                                       const float* __restrict__ out_w1,
                                       const float* __restrict__ out_w2) {
    int i = blockIdx.x * blockDim.x + threadIdx.x;
    if (i == 0) g_tile_ctr = 0;
    if (i < NOBS * NH) g_enc_w[i]  = __float2bfloat16(enc_w[i]);
    if (i < NH * NH)   g_out_w1[i] = __float2bfloat16(out_w1[i]);
    if (i < NH * NACT) g_out_w2[i] = __float2bfloat16(out_w2[i]);
    if (i < NROUNDS * NH * NH) {
        int r = i / (NH * NH);
        int k = (i / NH) & (NH - 1);
        int j = i & (NH - 1);
        float top = comm_w[r * 2 * NH * NH + k * NH + j];
        float bot = comm_w[r * 2 * NH * NH + (NH + k) * NH + j];
        g_comm_w1[i] = __float2bfloat16(top - bot * (1.0f / 31.0f));
        g_comm_w2[i] = __float2bfloat16(bot * (1.0f / 31.0f));
    }
}

// ---------------------------------------------------------------------------
// PTX helpers
// ---------------------------------------------------------------------------
__device__ __forceinline__ uint32_t smem_u32(const void* p) {
    return (uint32_t)__cvta_generic_to_shared(p);
}
__device__ __forceinline__ void cp16(void* dst, const void* src) {
    asm volatile("cp.async.cg.shared.global [%0], [%1], 16;"
                 :: "r"(smem_u32(dst)), "l"(src));
}
__device__ __forceinline__ void cp_commit() { asm volatile("cp.async.commit_group;"); }
__device__ __forceinline__ void cp_wait_all() { asm volatile("cp.async.wait_group 0;"); }
__device__ __forceinline__ void l2pf(const void* p) {
    asm volatile("prefetch.global.L2 [%0];" :: "l"(p));
}

__device__ __forceinline__ void ldsm_x4_t(uint32_t& r0, uint32_t& r1, uint32_t& r2, uint32_t& r3, uint32_t a) {
    asm volatile("ldmatrix.sync.aligned.m8n8.x4.trans.shared.b16 {%0,%1,%2,%3}, [%4];"
                 : "=r"(r0), "=r"(r1), "=r"(r2), "=r"(r3) : "r"(a));
}
__device__ __forceinline__ void mma16816(float* c,
                                         uint32_t a0, uint32_t a1, uint32_t a2, uint32_t a3,
                                         uint32_t b0, uint32_t b1) {
    asm volatile("mma.sync.aligned.m16n8k16.row.col.f32.bf16.bf16.f32 "
                 "{%0,%1,%2,%3}, {%4,%5,%6,%7}, {%8,%9}, {%0,%1,%2,%3};"
                 : "+f"(c[0]), "+f"(c[1]), "+f"(c[2]), "+f"(c[3])
                 : "r"(a0), "r"(a1), "r"(a2), "r"(a3), "r"(b0), "r"(b1));
}

__device__ __forceinline__ uint32_t packbf(float x, float y) {
    __nv_bfloat162 p = __floats2bfloat162_rn(x, y);
    return *(uint32_t*)&p;
}
__device__ __forceinline__ uint32_t bf2add(uint32_t a, uint32_t b) {
    __nv_bfloat162 r = __hadd2(*(__nv_bfloat162*)&a, *(__nv_bfloat162*)&b);
    return *(uint32_t*)&r;
}

// One K=16 step, single A fragment, NT n-tiles (8 cols each)
template <int NT>
__device__ __forceinline__ void gemm_ktile(const uint32_t a[4],
                                           const __nv_bfloat16* sWk, int wstride,
                                           float acc[][4], int lane) {
#pragma unroll
    for (int nt = 0; nt < NT; nt += 2) {
        uint32_t b0, b1, b2, b3;
        ldsm_x4_t(b0, b1, b2, b3,
                  smem_u32(sWk + (lane & 15) * wstride + nt * 8 + ((lane >> 4) << 3)));
        mma16816(acc[nt], a[0], a[1], a[2], a[3], b0, b1);
        if (nt + 1 < NT) mma16816(acc[nt + 1], a[0], a[1], a[2], a[3], b2, b3);
    }
}

// One K=16 step for two stripes: B loaded once, used by 2 A fragments.
template <int NT>
__device__ __forceinline__ void gemm2_ktile(const uint32_t a0[4], const uint32_t a1[4],
                                            const __nv_bfloat16* sWk, int wstride,
                                            float acc0[][4], float acc1[][4], int lane) {
#pragma unroll
    for (int nt = 0; nt < NT; nt += 2) {
        uint32_t b0, b1, b2, b3;
        ldsm_x4_t(b0, b1, b2, b3,
                  smem_u32(sWk + (lane & 15) * wstride + nt * 8 + ((lane >> 4) << 3)));
        mma16816(acc0[nt], a0[0], a0[1], a0[2], a0[3], b0, b1);
        mma16816(acc1[nt], a1[0], a1[1], a1[2], a1[3], b0, b1);
        if (nt + 1 < NT) {
            mma16816(acc0[nt + 1], a0[0], a0[1], a0[2], a0[3], b2, b3);
            mma16816(acc1[nt + 1], a1[0], a1[1], a1[2], a1[3], b2, b3);
        }
    }
}

// bias + relu + pack a 32-col half (acc[4][4]) into 2 A-frag k-tiles (bf16x2 ops).
__device__ __forceinline__ void pack_h4(const float acc[][4], uint32_t hf[][4],
                                        const uint32_t* sBH, int c) {
    const __nv_bfloat162 z = __float2bfloat162_rn(0.0f);
#pragma unroll
    for (int tt = 0; tt < 2; ++tt) {
        uint32_t bA = sBH[8 * tt + c];
        uint32_t bB = sBH[8 * tt + 4 + c];
#pragma unroll
        for (int j = 0; j < 2; ++j) {
            uint32_t pa = packbf(acc[2*tt][2*j],   acc[2*tt][2*j + 1]);
            uint32_t pb = packbf(acc[2*tt+1][2*j], acc[2*tt+1][2*j + 1]);
            __nv_bfloat162 ra = __hmax2(__hadd2(*(__nv_bfloat162*)&pa, *(__nv_bfloat162*)&bA), z);
            __nv_bfloat162 rb = __hmax2(__hadd2(*(__nv_bfloat162*)&pb, *(__nv_bfloat162*)&bB), z);
            hf[tt][j]     = *(uint32_t*)&ra;
            hf[tt][2 + j] = *(uint32_t*)&rb;
        }
    }
}

// Direct obs A-fragment gather (LDG.64 per fragment pair; L2-prefetched, no shfl)
__device__ __forceinline__ void enc_frags(const float* __restrict__ obs,
                                          size_t rbase_row, int t,
                                          int gr, int c, uint32_t a[4]) {
    const float* p = obs + (rbase_row + gr) * NOBS + 16 * t + 2 * c;
    float2 v0 = __ldg((const float2*)(p));
    float2 v1 = __ldg((const float2*)(p + 8 * NOBS));
    float2 v2 = __ldg((const float2*)(p + 8));
    float2 v3 = __ldg((const float2*)(p + 8 * NOBS + 8));
    a[0] = packbf(v0.x, v0.y);
    a[1] = packbf(v1.x, v1.y);
    a[2] = packbf(v2.x, v2.y);
    a[3] = packbf(v3.x, v3.y);
}

// Dense relu layer, N split into two 32-col halves (acc stays 32 regs)
__device__ __forceinline__ void dense64(const uint32_t (&ain)[2][4][4],
                                        uint32_t (&hout)[2][4][4],
                                        const __nv_bfloat16* W, const uint32_t* sBH,
                                        int lane, int c) {
#pragma unroll
    for (int nh = 0; nh < 2; ++nh) {
        float acc[2][4][4];
#pragma unroll
        for (int st = 0; st < 2; ++st)
#pragma unroll
            for (int nt = 0; nt < 4; ++nt) {
                acc[st][nt][0]=0.f; acc[st][nt][1]=0.f; acc[st][nt][2]=0.f; acc[st][nt][3]=0.f;
            }
#pragma unroll
        for (int t = 0; t < 4; ++t)
            gemm2_ktile<4>(ain[0][t], ain[1][t], W + 16 * t * W_STRIDE + 32 * nh, W_STRIDE,
                           acc[0], acc[1], lane);
        pack_h4(acc[0], &hout[0][2 * nh], sBH + 16 * nh, c);
        pack_h4(acc[1], &hout[1][2 * nh], sBH + 16 * nh, c);
    }
}

// Comm round (rank-1 decomposed). Column sums entirely in packed bf16 (HADD2).
__device__ __forceinline__ void comm_round(const uint32_t (&hin)[2][4][4],
                                           uint32_t (&hout)[2][4][4],
                                           const __nv_bfloat16* Wc1, const __nv_bfloat16* Wc2,
                                           const uint32_t* sBH, int lane, int c) {
    uint32_t csPA[4], csPB[4];
#pragma unroll
    for (int t = 0; t < 4; ++t) {
        uint32_t pA = bf2add(bf2add(hin[0][t][0], hin[0][t][1]),
                             bf2add(hin[1][t][0], hin[1][t][1]));
        uint32_t pB = bf2add(bf2add(hin[0][t][2], hin[0][t][3]),
                             bf2add(hin[1][t][2], hin[1][t][3]));
#pragma unroll
        for (int m = 4; m < 32; m <<= 1) {
            pA = bf2add(pA, __shfl_xor_sync(0xffffffffu, pA, m));
            pB = bf2add(pB, __shfl_xor_sync(0xffffffffu, pB, m));
        }
        csPA[t] = pA;
        csPB[t] = pB;
    }

#pragma unroll
    for (int nh = 0; nh < 2; ++nh) {
        // R = cs @ W2' (replicated-A, row-invariant) for this half
        float racc[4][4];
#pragma unroll
        for (int nt = 0; nt < 4; ++nt) {
            racc[nt][0]=0.f; racc[nt][1]=0.f; racc[nt][2]=0.f; racc[nt][3]=0.f;
        }
#pragma unroll
        for (int t = 0; t < 4; ++t) {
            uint32_t a[4];
            a[0] = csPA[t]; a[1] = csPA[t];
            a[2] = csPB[t]; a[3] = csPB[t];
            gemm_ktile<4>(a, Wc2 + 16 * t * W_STRIDE + 32 * nh, W_STRIDE, racc, lane);
        }
        // acc = R (all rows equal) + h @ W1'
        float acc[2][4][4];
#pragma unroll
        for (int st = 0; st < 2; ++st)
#pragma unroll
            for (int nt = 0; nt < 4; ++nt) {
                acc[st][nt][0]=racc[nt][0]; acc[st][nt][1]=racc[nt][1];
                acc[st][nt][2]=racc[nt][2]; acc[st][nt][3]=racc[nt][3];
            }
#pragma unroll
        for (int t = 0; t < 4; ++t)
            gemm2_ktile<4>(hin[0][t], hin[1][t], Wc1 + 16 * t * W_STRIDE + 32 * nh, W_STRIDE,
                           acc[0], acc[1], lane);
        pack_h4(acc[0], &hout[0][2 * nh], sBH + 16 * nh, c);
        pack_h4(acc[1], &hout[1][2 * nh], sBH + 16 * nh, c);
    }
}

// ---------------------------------------------------------------------------
// Persistent warp-autonomous CommNet kernel: 16 warps, 1 batch/warp, N-split
// ---------------------------------------------------------------------------
__global__ void __launch_bounds__(NTHREADS, 1)
commnet_kernel(const float* __restrict__ obs,
               const float* __restrict__ enc_b,
               const float* __restrict__ comm_b,
               const float* __restrict__ out_b1,
               const float* __restrict__ out_b2,
               const int*   __restrict__ avail,
               float*       __restrict__ out) {
    extern __shared__ __align__(16) char smem_raw[];
    __nv_bfloat16* sWe  = (__nv_bfloat16*)smem_raw;                  // 64  x 72
    __nv_bfloat16* sWc1 = sWe  + NH * W_STRIDE;                      // 128 x 72 (2 rounds)
    __nv_bfloat16* sWc2 = sWc1 + NROUNDS * NH * W_STRIDE;            // 128 x 72 (2 rounds)
    __nv_bfloat16* sWo1 = sWc2 + NROUNDS * NH * W_STRIDE;            // 64  x 72
    __nv_bfloat16* sWo2 = sWo1 + NH * W_STRIDE;                      // 64  x 24
    uint32_t*      sBH  = (uint32_t*)(sWo2 + NH * W2_STRIDE);        // 128 bf16x2 pairs
    float*         sB2  = (float*)(sBH + 128);                       // 16 fp32 (out_b2)

    const int tid  = threadIdx.x;
    const int lane = tid & 31;
    const int c    = lane & 3;
    const int gr   = lane >> 2;

    // ---- prologue: stage weights via cp.async, biases packed to bf16x2 ----
    for (int i = tid; i < 512; i += NTHREADS) {
        int r = i >> 3, ci = i & 7;
        cp16(sWe + r * W_STRIDE + ci * 8, g_enc_w + r * NH + ci * 8);
    }
    for (int i = tid; i < 1024; i += NTHREADS) {
        int r = i >> 3, ci = i & 7;
        cp16(sWc1 + r * W_STRIDE + ci * 8, g_comm_w1 + r * NH + ci * 8);
    }
    for (int i = tid; i < 1024; i += NTHREADS) {
        int r = i >> 3, ci = i & 7;
        cp16(sWc2 + r * W_STRIDE + ci * 8, g_comm_w2 + r * NH + ci * 8);
    }
    for (int i = tid; i < 512; i += NTHREADS) {
        int r = i >> 3, ci = i & 7;
        cp16(sWo1 + r * W_STRIDE + ci * 8, g_out_w1 + r * NH + ci * 8);
    }
    for (int i = tid; i < 128; i += NTHREADS) {
        int r = i >> 1, ci = i & 1;
        cp16(sWo2 + r * W2_STRIDE + ci * 8, g_out_w2 + r * NACT + ci * 8);
    }
    cp_commit();
    // bias pairs: enc [0..32), comm rd0 [32..64), comm rd1 [64..96), out1 [96..128)
    if (tid < 32) sBH[tid]      = packbf(enc_b[2*tid],  enc_b[2*tid+1]);
    if (tid < 64) sBH[32 + tid] = packbf(comm_b[2*tid], comm_b[2*tid+1]);
    if (tid < 32) sBH[96 + tid] = packbf(out_b1[2*tid], out_b1[2*tid+1]);
    if (tid < 16) sB2[tid]      = out_b2[tid];
    cp_wait_all();
    __syncthreads();

    // ---- per-warp batch loop ----
    unsigned b;
    if (lane == 0) b = atomicAdd(&g_tile_ctr, 1u);
    b = __shfl_sync(0xffffffffu, b, 0);

    uint32_t hA[2][4][4], hB[2][4][4];   // ping-pong activation fragments

    while (b < NUNITS) {
        const size_t row0 = (size_t)b * NAG;

        // ---- encoder: hA = relu(obs @ enc_w + enc_b) ----
        {
            uint32_t ofrag[2][4][4];
#pragma unroll
            for (int t = 0; t < 4; ++t) {
                enc_frags(obs, row0,      t, gr, c, ofrag[0][t]);
                enc_frags(obs, row0 + 16, t, gr, c, ofrag[1][t]);
            }
            dense64(ofrag, hA, sWe, sBH, lane, c);
        }

        // ---- grab next batch, prefetch its obs+avail to L2 ----
        unsigned bn;
        if (lane == 0) bn = atomicAdd(&g_tile_ctr, 1u);
        bn = __shfl_sync(0xffffffffu, bn, 0);
        if (bn < NUNITS) {
            const char* ob = (const char*)(obs + (size_t)bn * NAG * NOBS);
#pragma unroll
            for (int i = 0; i < 2; ++i) l2pf(ob + lane * 128 + i * 4096);
            if (lane < 16) l2pf((const char*)(avail + (size_t)bn * NAG * NACT) + lane * 128);
        }

        // ---- comm rounds: hA -> hB -> hA ----
        comm_round(hA, hB, sWc1,                 sWc2,                 sBH + 32, lane, c);
        comm_round(hB, hA, sWc1 + NH * W_STRIDE, sWc2 + NH * W_STRIDE, sBH + 64, lane, c);

        // ---- out1: hB = relu(hA @ out_w1 + out_b1) ----
        dense64(hA, hB, sWo1, sBH + 96, lane, c);

        // ---- hoist avail loads (overlap L2 latency with out2 MMAs) ----
        int2 av[2][2][2];
        {
            int colb = 2 * c;
#pragma unroll
            for (int st = 0; st < 2; ++st)
#pragma unroll
                for (int nt = 0; nt < 2; ++nt)
#pragma unroll
                    for (int half = 0; half < 2; ++half) {
                        size_t grow = row0 + st * 16 + gr + 8 * half;
                        av[st][nt][half] = __ldg((const int2*)(avail + grow * NACT + nt * 8 + colb));
                    }
        }

        // ---- out2 from hB: q = hid @ out_w2 + out_b2, mask, store ----
        float acc2[2][2][4];
#pragma unroll
        for (int st = 0; st < 2; ++st)
#pragma unroll
            for (int nt = 0; nt < 2; ++nt) {
                acc2[st][nt][0]=0.f; acc2[st][nt][1]=0.f; acc2[st][nt][2]=0.f; acc2[st][nt][3]=0.f;
            }
#pragma unroll
        for (int t = 0; t < 4; ++t) {
            uint32_t b0, b1, b2, b3;
            ldsm_x4_t(b0, b1, b2, b3,
                      smem_u32(sWo2 + (16 * t + (lane & 15)) * W2_STRIDE + ((lane >> 4) << 3)));
#pragma unroll
            for (int st = 0; st < 2; ++st) {
                const uint32_t* A = hB[st][t];
                mma16816(acc2[st][0], A[0], A[1], A[2], A[3], b0, b1);
                mma16816(acc2[st][1], A[0], A[1], A[2], A[3], b2, b3);
            }
        }

        // ---- epilogue: bias + mask + store ----
        {
            int colb = 2 * c;
#pragma unroll
            for (int st = 0; st < 2; ++st) {
                size_t rowb = row0 + st * 16;
#pragma unroll
                for (int nt = 0; nt < 2; ++nt) {
                    int col  = nt * 8 + colb;
                    float b0 = sB2[col], b1 = sB2[col + 1];
#pragma unroll
                    for (int half = 0; half < 2; ++half) {
                        size_t grow = rowb + gr + 8 * half;
                        int2 a = av[st][nt][half];
                        float q0 = acc2[st][nt][half * 2 + 0] + b0;
                        float q1 = acc2[st][nt][half * 2 + 1] + b1;
                        if (a.x == 0) q0 = -1e10f;
                        if (a.y == 0) q1 = -1e10f;
                        *(float2*)(out + grow * NACT + col) = make_float2(q0, q1);
                    }
                }
            }
        }

        b = bn;
    }
}

#define SMEM_BYTES ((64*72 + 2*64*72 + 2*64*72 + 64*72 + 64*24) * 2 + 128 * 4 + 16 * 4 + 64)

// ---------------------------------------------------------------------------
extern "C" void kernel_launch(void* const* d_in, const int* in_sizes, int n_in,
                              void* d_out, int out_size) {
    const float* obs    = (const float*)d_in[0];
    const float* enc_w  = (const float*)d_in[1];
    const float* enc_b  = (const float*)d_in[2];
    const float* comm_w = (const float*)d_in[3];
    const float* comm_b = (const float*)d_in[4];
    const float* out_w1 = (const float*)d_in[5];
    const float* out_b1 = (const float*)d_in[6];
    const float* out_w2 = (const float*)d_in[7];
    const float* out_b2 = (const float*)d_in[8];
    const int*   avail  = (const int*)d_in[9];
    float* out = (float*)d_out;

    cudaFuncSetAttribute(commnet_kernel, cudaFuncAttributeMaxDynamicSharedMemorySize, SMEM_BYTES);

    convert_weights_kernel<<<64, 256>>>(enc_w, comm_w, out_w1, out_w2);
    commnet_kernel<<<NCTAS, NTHREADS, SMEM_BYTES>>>(
        obs, enc_b, comm_b, out_b1, out_b2, avail, out);
}